// round 1
// baseline (speedup 1.0000x reference)
#include <cuda_runtime.h>
#include <math.h>

#define PP 7
#define SSUB 4
#define NBIN 49
#define CCH 128
#define HH 160
#define WW 160
#define NROI 256
#define KX 6272          // C*P*P
#define DFF 1024
#define SCALE_ 0.0625f
#define TSTD 0.1f
#define HWSZ (HH*WW)

// ---------------- scratch (device globals; no runtime allocation) ----------------
__device__ float g_nhwc[2 * HWSZ * CCH];          // 26.2 MB
__device__ float g_x[NROI * KX];                  // pooled features (N, C*49)
__device__ float g_p1[2 * NROI * 2048];           // split-K partials for x@[w1|wm1]
__device__ float g_h1[NROI * DFF];
__device__ float g_m[NROI * DFF];
__device__ float g_p2[4 * NROI * DFF];            // split-K partials for h1@w2
__device__ float g_h2[NROI * DFF];
__device__ float g_off[NROI * 98];
__device__ float g_mask[NROI * NBIN];

// ---------------- NCHW -> NHWC transpose ----------------
__global__ void k_nchw2nhwc(const float* __restrict__ in) {
    __shared__ float t[32][33];
    int b   = blockIdx.z;
    int hw0 = blockIdx.x * 32;
    int c0  = blockIdx.y * 32;
    int tx = threadIdx.x, ty = threadIdx.y;
#pragma unroll
    for (int i = 0; i < 32; i += 8)
        t[ty + i][tx] = in[(size_t)(b * CCH + c0 + ty + i) * HWSZ + hw0 + tx];
    __syncthreads();
#pragma unroll
    for (int i = 0; i < 32; i += 8)
        g_nhwc[(size_t)(b * HWSZ + hw0 + ty + i) * CCH + c0 + tx] = t[tx][ty + i];
}

// ---------------- deformable PSROI pool ----------------
// grid.x = NROI*49, block = 32 threads (each thread: 4 channels via float4)
// trans: (N,2,7,7) offsets or nullptr; maskp: (N,49) or nullptr.
// out layout: (N, C, 7, 7)  == (N, C*49) row-major, which is exactly x's layout.
__global__ void k_pool(const float* __restrict__ rois,
                       const float* __restrict__ trans,
                       const float* __restrict__ maskp,
                       float* __restrict__ out) {
    int bin = blockIdx.x;
    int n  = bin / NBIN;
    int s  = bin - n * NBIN;
    int ph = s / PP;
    int pw = s - ph * PP;

    const float* r = rois + n * 5;
    int   bi = (int)r[0];
    float x1 = rintf(r[1]) * SCALE_ - 0.5f;
    float y1 = rintf(r[2]) * SCALE_ - 0.5f;
    float x2 = (rintf(r[3]) + 1.0f) * SCALE_ - 0.5f;
    float y2 = (rintf(r[4]) + 1.0f) * SCALE_ - 0.5f;
    float roiw = fmaxf(x2 - x1, 0.1f);
    float roih = fmaxf(y2 - y1, 0.1f);
    float binw = __fdiv_rn(roiw, 7.0f);
    float binh = __fdiv_rn(roih, 7.0f);
    float subw = binw * 0.25f;
    float subh = binh * 0.25f;

    float tx = 0.0f, ty = 0.0f;
    if (trans) {
        tx = trans[n * 98 + s] * TSTD;
        ty = trans[n * 98 + 49 + s] * TSTD;
    }
    float wst = (float)pw * binw + x1 + tx * roiw;
    float hst = (float)ph * binh + y1 + ty * roih;

    int c4 = threadIdx.x;             // 0..31 -> channels c4*4 .. c4*4+3
    float4 acc = make_float4(0.f, 0.f, 0.f, 0.f);
    int cnt = 0;

    const float* base = g_nhwc + (size_t)bi * HWSZ * CCH;

    for (int ih = 0; ih < SSUB; ih++) {
        float h = hst + (float)ih * subh;
        for (int iw = 0; iw < SSUB; iw++) {
            float w = wst + (float)iw * subw;
            if (w < -0.5f || w > (float)WW - 0.5f ||
                h < -0.5f || h > (float)HH - 0.5f) continue;
            cnt++;
            float wc = fminf(fmaxf(w, 0.f), (float)WW - 1.f);
            float hc = fminf(fmaxf(h, 0.f), (float)HH - 1.f);
            int xx0 = (int)floorf(wc);
            int yy0 = (int)floorf(hc);
            int xx1 = min(xx0 + 1, WW - 1);
            int yy1 = min(yy0 + 1, HH - 1);
            float lx = wc - (float)xx0;
            float ly = hc - (float)yy0;
            float w00 = (1.f - ly) * (1.f - lx);
            float w01 = (1.f - ly) * lx;
            float w10 = ly * (1.f - lx);
            float w11 = ly * lx;

            const float4* p00 = (const float4*)(base + (size_t)(yy0 * WW + xx0) * CCH) + c4;
            const float4* p01 = (const float4*)(base + (size_t)(yy0 * WW + xx1) * CCH) + c4;
            const float4* p10 = (const float4*)(base + (size_t)(yy1 * WW + xx0) * CCH) + c4;
            const float4* p11 = (const float4*)(base + (size_t)(yy1 * WW + xx1) * CCH) + c4;
            float4 v00 = __ldg(p00);
            float4 v01 = __ldg(p01);
            float4 v10 = __ldg(p10);
            float4 v11 = __ldg(p11);
            acc.x += w00 * v00.x + w01 * v01.x + w10 * v10.x + w11 * v11.x;
            acc.y += w00 * v00.y + w01 * v01.y + w10 * v10.y + w11 * v11.y;
            acc.z += w00 * v00.z + w01 * v01.z + w10 * v10.z + w11 * v11.z;
            acc.w += w00 * v00.w + w01 * v01.w + w10 * v10.w + w11 * v11.w;
        }
    }

    float scale = (cnt > 0) ? __fdiv_rn(1.0f, (float)cnt) : 0.0f;
    if (maskp) scale *= maskp[n * NBIN + s];
    float vals[4] = {acc.x * scale, acc.y * scale, acc.z * scale, acc.w * scale};
    int cbase = c4 * 4;
#pragma unroll
    for (int j = 0; j < 4; j++)
        out[(size_t)(n * CCH + cbase + j) * NBIN + s] = vals[j];
}

// ---------------- 64x128-tile split-K FP32 GEMM ----------------
// A: (256, lda) row-major.  B selected by column block: cols [0,ncols0) -> B0,
// cols [ncols0, 2*ncols0) -> B1 (both row-major, ld = ncols0).
// Writes raw partials to part[blockIdx.z][256][ldp]. No bias/activation here.
__global__ void __launch_bounds__(128) k_gemm(
    const float* __restrict__ A, int lda,
    const float* __restrict__ B0, const float* __restrict__ B1, int ncols0,
    int kper, float* __restrict__ part, int ldp) {
    __shared__ float As[16][64];
    __shared__ float Bs[16][128];

    int tid = threadIdx.x;
    int m0 = blockIdx.y * 64;
    int n0 = blockIdx.x * 128;
    int kbeg = blockIdx.z * kper;
    int kend = kbeg + kper;

    const float* Bm = (n0 < ncols0) ? B0 : B1;
    int bn0 = (n0 < ncols0) ? n0 : (n0 - ncols0);

    int ra = tid >> 2;             // 0..31
    int ca = (tid & 3) << 2;       // 0,4,8,12
    int rb = tid >> 5;             // 0..3
    int cb = (tid & 31) << 2;      // 0..124
    int nid = tid & 15;
    int mid = tid >> 4;

    const float* Ap0 = A + (size_t)(m0 + ra) * lda + ca;
    const float* Ap1 = A + (size_t)(m0 + ra + 32) * lda + ca;
    const float* Bp  = Bm + (size_t)rb * ncols0 + bn0 + cb;

    float acc[8][8];
#pragma unroll
    for (int i = 0; i < 8; i++)
#pragma unroll
        for (int j = 0; j < 8; j++) acc[i][j] = 0.f;

    float4 pa0, pa1, pb0, pb1, pb2, pb3;

    // prologue fetch (tile at kbeg)
    {
        int k = kbeg;
        pa0 = *(const float4*)(Ap0 + k);
        pa1 = *(const float4*)(Ap1 + k);
        const float* bp = Bp + (size_t)k * ncols0;
        pb0 = *(const float4*)(bp);
        pb1 = *(const float4*)(bp + 4 * ncols0);
        pb2 = *(const float4*)(bp + 8 * ncols0);
        pb3 = *(const float4*)(bp + 12 * ncols0);
    }
    // store tile 0
    As[ca + 0][ra] = pa0.x; As[ca + 1][ra] = pa0.y;
    As[ca + 2][ra] = pa0.z; As[ca + 3][ra] = pa0.w;
    As[ca + 0][ra + 32] = pa1.x; As[ca + 1][ra + 32] = pa1.y;
    As[ca + 2][ra + 32] = pa1.z; As[ca + 3][ra + 32] = pa1.w;
    *(float4*)&Bs[rb][cb]      = pb0;
    *(float4*)&Bs[rb + 4][cb]  = pb1;
    *(float4*)&Bs[rb + 8][cb]  = pb2;
    *(float4*)&Bs[rb + 12][cb] = pb3;
    __syncthreads();

    for (int k = kbeg + 16; ; k += 16) {
        bool more = (k < kend);
        if (more) {
            pa0 = *(const float4*)(Ap0 + k);
            pa1 = *(const float4*)(Ap1 + k);
            const float* bp = Bp + (size_t)k * ncols0;
            pb0 = *(const float4*)(bp);
            pb1 = *(const float4*)(bp + 4 * ncols0);
            pb2 = *(const float4*)(bp + 8 * ncols0);
            pb3 = *(const float4*)(bp + 12 * ncols0);
        }
#pragma unroll
        for (int kk = 0; kk < 16; kk++) {
            float4 a0 = *(const float4*)&As[kk][mid * 8];
            float4 a1 = *(const float4*)&As[kk][mid * 8 + 4];
            float4 b0 = *(const float4*)&Bs[kk][nid * 4];
            float4 b1 = *(const float4*)&Bs[kk][64 + nid * 4];
            float av[8] = {a0.x, a0.y, a0.z, a0.w, a1.x, a1.y, a1.z, a1.w};
            float bv[8] = {b0.x, b0.y, b0.z, b0.w, b1.x, b1.y, b1.z, b1.w};
#pragma unroll
            for (int i = 0; i < 8; i++)
#pragma unroll
                for (int j = 0; j < 8; j++)
                    acc[i][j] += av[i] * bv[j];
        }
        if (!more) break;
        __syncthreads();
        As[ca + 0][ra] = pa0.x; As[ca + 1][ra] = pa0.y;
        As[ca + 2][ra] = pa0.z; As[ca + 3][ra] = pa0.w;
        As[ca + 0][ra + 32] = pa1.x; As[ca + 1][ra + 32] = pa1.y;
        As[ca + 2][ra + 32] = pa1.z; As[ca + 3][ra + 32] = pa1.w;
        *(float4*)&Bs[rb][cb]      = pb0;
        *(float4*)&Bs[rb + 4][cb]  = pb1;
        *(float4*)&Bs[rb + 8][cb]  = pb2;
        *(float4*)&Bs[rb + 12][cb] = pb3;
        __syncthreads();
    }

    float* cbase = part + (size_t)blockIdx.z * NROI * ldp;
#pragma unroll
    for (int i = 0; i < 8; i++) {
        int m = m0 + mid * 8 + i;
        float4 o0 = make_float4(acc[i][0], acc[i][1], acc[i][2], acc[i][3]);
        float4 o1 = make_float4(acc[i][4], acc[i][5], acc[i][6], acc[i][7]);
        *(float4*)(cbase + (size_t)m * ldp + n0 + nid * 4)      = o0;
        *(float4*)(cbase + (size_t)m * ldp + n0 + 64 + nid * 4) = o1;
    }
}

// ---------------- split-K reductions (+bias +relu) ----------------
__global__ void k_reduce2(const float* __restrict__ part,
                          const float* __restrict__ bias0,
                          const float* __restrict__ bias1,
                          float* __restrict__ o0, float* __restrict__ o1) {
    int i = blockIdx.x * 256 + threadIdx.x;   // over 256*2048
    int n = i & 2047;
    int m = i >> 11;
    float v = part[i] + part[NROI * 2048 + i];
    if (n < 1024) o0[m * 1024 + n] = fmaxf(v + bias0[n], 0.f);
    else          o1[m * 1024 + (n - 1024)] = fmaxf(v + bias1[n - 1024], 0.f);
}

__global__ void k_reduce4(const float* __restrict__ part,
                          const float* __restrict__ bias,
                          float* __restrict__ o) {
    int i = blockIdx.x * 256 + threadIdx.x;   // over 256*1024
    const int S = NROI * DFF;
    float v = part[i] + part[S + i] + part[2 * S + i] + part[3 * S + i];
    int n = i & 1023;
    o[i] = fmaxf(v + bias[n], 0.f);
}

// ---------------- small-N GEMM (N<=128): out = act(A@B + bias) ----------------
// grid.x = 256/16 = 16 (row blocks of 16), block = 128 threads (one col each).
__global__ void k_small_gemm(const float* __restrict__ A,
                             const float* __restrict__ Bm,
                             const float* __restrict__ bias,
                             float* __restrict__ Cm,
                             int K, int Nn, int act) {
    __shared__ float As[16][128];
    int tid = threadIdx.x;
    int m0 = blockIdx.x * 16;
    float acc[16];
#pragma unroll
    for (int i = 0; i < 16; i++) acc[i] = 0.f;

    for (int kc = 0; kc < K; kc += 128) {
#pragma unroll
        for (int q = 0; q < 16; q++)
            As[q][tid] = A[(size_t)(m0 + q) * K + kc + tid];
        __syncthreads();
        if (tid < Nn) {
            for (int k = 0; k < 128; k++) {
                float bv = Bm[(size_t)(kc + k) * Nn + tid];
#pragma unroll
                for (int i = 0; i < 16; i++) acc[i] += As[i][k] * bv;
            }
        }
        __syncthreads();
    }
    if (tid < Nn) {
        float bb = bias[tid];
#pragma unroll
        for (int i = 0; i < 16; i++) {
            float v = acc[i] + bb;
            if (act == 1) v = fmaxf(v, 0.f);
            else if (act == 2) v = 1.0f / (1.0f + expf(-v));
            Cm[(size_t)(m0 + i) * Nn + tid] = v;
        }
    }
}

// ---------------- launch ----------------
extern "C" void kernel_launch(void* const* d_in, const int* in_sizes, int n_in,
                              void* d_out, int out_size) {
    const float* data = (const float*)d_in[0];
    const float* rois = (const float*)d_in[1];
    const float* w1   = (const float*)d_in[2];
    const float* b1   = (const float*)d_in[3];
    const float* w2   = (const float*)d_in[4];
    const float* b2   = (const float*)d_in[5];
    const float* w3   = (const float*)d_in[6];
    const float* b3   = (const float*)d_in[7];
    const float* wm1  = (const float*)d_in[8];
    const float* bm1  = (const float*)d_in[9];
    const float* wm2  = (const float*)d_in[10];
    const float* bm2  = (const float*)d_in[11];
    float* out = (float*)d_out;

    void *px, *pp1, *ph1, *pm, *pp2, *ph2, *poff, *pmask;
    cudaGetSymbolAddress(&px,    g_x);
    cudaGetSymbolAddress(&pp1,   g_p1);
    cudaGetSymbolAddress(&ph1,   g_h1);
    cudaGetSymbolAddress(&pm,    g_m);
    cudaGetSymbolAddress(&pp2,   g_p2);
    cudaGetSymbolAddress(&ph2,   g_h2);
    cudaGetSymbolAddress(&poff,  g_off);
    cudaGetSymbolAddress(&pmask, g_mask);

    // 1) NCHW -> NHWC
    k_nchw2nhwc<<<dim3(HWSZ / 32, CCH / 32, 2), dim3(32, 8)>>>(data);

    // 2) pool #1 (no offsets, no mask) -> x
    k_pool<<<NROI * NBIN, 32>>>(rois, nullptr, nullptr, (float*)px);

    // 3) fused big GEMM: x @ [w1 | wm1], split-K=2
    k_gemm<<<dim3(16, 4, 2), 128>>>((const float*)px, KX, w1, wm1, 1024, KX / 2,
                                    (float*)pp1, 2048);
    // 4) reduce + bias + relu -> h1, m
    k_reduce2<<<2048, 256>>>((const float*)pp1, b1, bm1, (float*)ph1, (float*)pm);

    // 5) h1 @ w2, split-K=4
    k_gemm<<<dim3(8, 4, 4), 128>>>((const float*)ph1, DFF, w2, w2, 1024, DFF / 4,
                                   (float*)pp2, 1024);
    // 6) reduce + bias + relu -> h2
    k_reduce4<<<1024, 256>>>((const float*)pp2, b2, (float*)ph2);

    // 7) offset = h2 @ w3 + b3
    k_small_gemm<<<16, 128>>>((const float*)ph2, w3, b3, (float*)poff, DFF, 98, 0);
    // 8) mask = sigmoid(m @ wm2 + bm2)
    k_small_gemm<<<16, 128>>>((const float*)pm, wm2, bm2, (float*)pmask, DFF, 49, 2);

    // 9) pool #2 with offsets, multiply by mask -> out
    k_pool<<<NROI * NBIN, 32>>>(rois, (const float*)poff, (const float*)pmask, out);
}

// round 4
// speedup vs baseline: 1.8707x; 1.8707x over previous
#include <cuda_runtime.h>
#include <cuda_bf16.h>
#include <math.h>
#include <stdint.h>

#define PP 7
#define SSUB 4
#define NBIN 49
#define CCH 128
#define HH 160
#define WW 160
#define NROI 256
#define KX 6272          // C*P*P
#define DFF 1024
#define SCALE_ 0.0625f
#define TSTD 0.1f
#define HWSZ (HH*WW)

// ---------------- scratch (device globals; no runtime allocation) ----------------
__device__ __align__(1024) float g_nhwc[2 * HWSZ * CCH];
__device__ __align__(1024) __nv_bfloat16 g_xh[NROI * KX];
__device__ __align__(1024) __nv_bfloat16 g_xl[NROI * KX];
__device__ __align__(1024) __nv_bfloat16 g_bt1h[2048 * KX];   // [w1|wm1]^T hi (N,K) K-major
__device__ __align__(1024) __nv_bfloat16 g_bt1l[2048 * KX];
__device__ __align__(1024) __nv_bfloat16 g_bt2h[DFF * DFF];   // w2^T
__device__ __align__(1024) __nv_bfloat16 g_bt2l[DFF * DFF];
__device__ __align__(1024) float g_p1[2 * NROI * 2048];       // split-K partials GEMM1
__device__ __align__(1024) __nv_bfloat16 g_h1h[NROI * DFF];
__device__ __align__(1024) __nv_bfloat16 g_h1l[NROI * DFF];
__device__ __align__(1024) float g_m[NROI * DFF];
__device__ __align__(1024) float g_p2[4 * NROI * DFF];        // split-K partials GEMM2
__device__ __align__(1024) float g_h2[NROI * DFF];
__device__ float g_off[NROI * 98];
__device__ float g_mask[NROI * NBIN];

// ================= PTX helpers (baseline ISA only: sm_80-class) =================
__device__ __forceinline__ uint32_t smem_u32(const void* p) {
    uint32_t a;
    asm("{ .reg .u64 t; cvta.to.shared.u64 t, %1; cvt.u32.u64 %0, t; }" : "=r"(a) : "l"(p));
    return a;
}
__device__ __forceinline__ void cp_async16(uint32_t dst, const void* src) {
    asm volatile("cp.async.cg.shared.global [%0], [%1], 16;" :: "r"(dst), "l"(src) : "memory");
}
#define CP_COMMIT() asm volatile("cp.async.commit_group;" ::: "memory")
#define CP_WAIT0()  asm volatile("cp.async.wait_group 0;" ::: "memory")

__device__ __forceinline__ void ldsm_x4(uint32_t* r, uint32_t addr) {
    asm volatile("ldmatrix.sync.aligned.m8n8.x4.shared.b16 {%0,%1,%2,%3}, [%4];"
                 : "=r"(r[0]), "=r"(r[1]), "=r"(r[2]), "=r"(r[3]) : "r"(addr));
}
__device__ __forceinline__ void mma16816(float* c, const uint32_t* a, uint32_t b0, uint32_t b1) {
    asm volatile(
        "mma.sync.aligned.m16n8k16.row.col.f32.bf16.bf16.f32 "
        "{%0,%1,%2,%3}, {%4,%5,%6,%7}, {%8,%9}, {%0,%1,%2,%3};"
        : "+f"(c[0]), "+f"(c[1]), "+f"(c[2]), "+f"(c[3])
        : "r"(a[0]), "r"(a[1]), "r"(a[2]), "r"(a[3]), "r"(b0), "r"(b1));
}

// ---------------- NCHW -> NHWC transpose ----------------
__global__ void k_nchw2nhwc(const float* __restrict__ in) {
    __shared__ float t[32][33];
    int b   = blockIdx.z;
    int hw0 = blockIdx.x * 32;
    int c0  = blockIdx.y * 32;
    int tx = threadIdx.x, ty = threadIdx.y;
#pragma unroll
    for (int i = 0; i < 32; i += 8)
        t[ty + i][tx] = in[(size_t)(b * CCH + c0 + ty + i) * HWSZ + hw0 + tx];
    __syncthreads();
#pragma unroll
    for (int i = 0; i < 32; i += 8)
        g_nhwc[(size_t)(b * HWSZ + hw0 + ty + i) * CCH + c0 + tx] = t[tx][ty + i];
}

// ---------------- weight transpose + bf16 hi/lo split ----------------
__global__ void k_cvt_t(const float* __restrict__ W, int Nn,
                        __nv_bfloat16* __restrict__ Th, __nv_bfloat16* __restrict__ Tl,
                        int ldt) {
    __shared__ float t[32][33];
    int k0 = blockIdx.x * 32, n0 = blockIdx.y * 32;
    int tx = threadIdx.x, ty = threadIdx.y;
#pragma unroll
    for (int i = 0; i < 32; i += 8)
        t[ty + i][tx] = W[(size_t)(k0 + ty + i) * Nn + n0 + tx];
    __syncthreads();
#pragma unroll
    for (int i = 0; i < 32; i += 8) {
        float v = t[tx][ty + i];                   // k = k0+tx, n = n0+ty+i
        __nv_bfloat16 h = __float2bfloat16(v);
        __nv_bfloat16 l = __float2bfloat16(v - __bfloat162float(h));
        size_t o = (size_t)(n0 + ty + i) * ldt + k0 + tx;
        Th[o] = h;
        Tl[o] = l;
    }
}

// ---------------- deformable PSROI pool ----------------
__global__ void k_pool(const float* __restrict__ rois,
                       const float* __restrict__ trans,
                       const float* __restrict__ maskp,
                       __nv_bfloat16* __restrict__ outh,
                       __nv_bfloat16* __restrict__ outl,
                       float* __restrict__ outf) {
    int bin = blockIdx.x;
    int n  = bin / NBIN;
    int s  = bin - n * NBIN;
    int ph = s / PP;
    int pw = s - ph * PP;

    const float* r = rois + n * 5;
    int   bi = (int)r[0];
    float x1 = rintf(r[1]) * SCALE_ - 0.5f;
    float y1 = rintf(r[2]) * SCALE_ - 0.5f;
    float x2 = (rintf(r[3]) + 1.0f) * SCALE_ - 0.5f;
    float y2 = (rintf(r[4]) + 1.0f) * SCALE_ - 0.5f;
    float roiw = fmaxf(x2 - x1, 0.1f);
    float roih = fmaxf(y2 - y1, 0.1f);
    float binw = __fdiv_rn(roiw, 7.0f);
    float binh = __fdiv_rn(roih, 7.0f);
    float subw = binw * 0.25f;
    float subh = binh * 0.25f;

    float tx = 0.0f, ty = 0.0f;
    if (trans) {
        tx = trans[n * 98 + s] * TSTD;
        ty = trans[n * 98 + 49 + s] * TSTD;
    }
    float wst = (float)pw * binw + x1 + tx * roiw;
    float hst = (float)ph * binh + y1 + ty * roih;

    int c4 = threadIdx.x;
    float4 acc = make_float4(0.f, 0.f, 0.f, 0.f);
    int cnt = 0;

    const float* base = g_nhwc + (size_t)bi * HWSZ * CCH;

    for (int ih = 0; ih < SSUB; ih++) {
        float h = hst + (float)ih * subh;
        for (int iw = 0; iw < SSUB; iw++) {
            float w = wst + (float)iw * subw;
            if (w < -0.5f || w > (float)WW - 0.5f ||
                h < -0.5f || h > (float)HH - 0.5f) continue;
            cnt++;
            float wc = fminf(fmaxf(w, 0.f), (float)WW - 1.f);
            float hc = fminf(fmaxf(h, 0.f), (float)HH - 1.f);
            int xx0 = (int)floorf(wc);
            int yy0 = (int)floorf(hc);
            int xx1 = min(xx0 + 1, WW - 1);
            int yy1 = min(yy0 + 1, HH - 1);
            float lx = wc - (float)xx0;
            float ly = hc - (float)yy0;
            float w00 = (1.f - ly) * (1.f - lx);
            float w01 = (1.f - ly) * lx;
            float w10 = ly * (1.f - lx);
            float w11 = ly * lx;

            float4 v00 = __ldg((const float4*)(base + (size_t)(yy0 * WW + xx0) * CCH) + c4);
            float4 v01 = __ldg((const float4*)(base + (size_t)(yy0 * WW + xx1) * CCH) + c4);
            float4 v10 = __ldg((const float4*)(base + (size_t)(yy1 * WW + xx0) * CCH) + c4);
            float4 v11 = __ldg((const float4*)(base + (size_t)(yy1 * WW + xx1) * CCH) + c4);
            acc.x += w00 * v00.x + w01 * v01.x + w10 * v10.x + w11 * v11.x;
            acc.y += w00 * v00.y + w01 * v01.y + w10 * v10.y + w11 * v11.y;
            acc.z += w00 * v00.z + w01 * v01.z + w10 * v10.z + w11 * v11.z;
            acc.w += w00 * v00.w + w01 * v01.w + w10 * v10.w + w11 * v11.w;
        }
    }

    float scale = (cnt > 0) ? __fdiv_rn(1.0f, (float)cnt) : 0.0f;
    if (maskp) scale *= maskp[n * NBIN + s];
    float vals[4] = {acc.x * scale, acc.y * scale, acc.z * scale, acc.w * scale};
    int cbase = c4 * 4;
    if (outf) {
#pragma unroll
        for (int j = 0; j < 4; j++)
            outf[(size_t)(n * CCH + cbase + j) * NBIN + s] = vals[j];
    } else {
#pragma unroll
        for (int j = 0; j < 4; j++) {
            size_t o = (size_t)(n * CCH + cbase + j) * NBIN + s;
            __nv_bfloat16 h = __float2bfloat16(vals[j]);
            outh[o] = h;
            outl[o] = __float2bfloat16(vals[j] - __bfloat162float(h));
        }
    }
}

// ---------------- bf16 hi/lo split-K GEMM via mma.sync (HMMA) ----------------
// C_partial[z] = Ah*Bh + Ah*Bl + Al*Bh over this split's K range.
// A: (M,K) K-major bf16; B: (N,K) K-major bf16.
// CTA tile 64x128, K-chunk 64, 256 thr = 8 warps (2 M x 4 N), warp tile 32x32.
// SMEM buffer (48KB x2): Ah@0 (64x64), Al@8K, Bh@16K (128x64), Bl@32K.
// Rows are 128B (64 bf16) with SW128 swizzle (seg^=(row&7)).
__global__ void __launch_bounds__(256)
k_mma(const __nv_bfloat16* __restrict__ Ah, const __nv_bfloat16* __restrict__ Al, int lda,
      const __nv_bfloat16* __restrict__ Bh, const __nv_bfloat16* __restrict__ Bl, int ldb,
      int kchunks, float* __restrict__ part, int ldp) {
    extern __shared__ __align__(1024) char dsm[];
    uint32_t sb = smem_u32(dsm);

    int tid = threadIdx.x;
    int lane = tid & 31;
    int w = tid >> 5;
    int warp_m = w & 1;           // 0..1 (32 rows each)
    int warp_n = w >> 1;          // 0..3 (32 cols each)
    int m0 = blockIdx.y * 64;
    int n0 = blockIdx.x * 128;
    int kbeg = blockIdx.z * kchunks * 64;

    // cp.async issue of one chunk into buffer b
    auto issue = [&](int b, int kelem) {
        uint32_t tb = sb + (uint32_t)b * 49152u;
        // A tiles: 64 rows x 128B = 512 segs; 2 per thread
#pragma unroll
        for (int i = 0; i < 2; i++) {
            int sidx = tid + i * 256;
            int row = sidx >> 3, seg = sidx & 7;
            uint32_t dst = tb + row * 128 + ((seg ^ (row & 7)) << 4);
            cp_async16(dst, Ah + (size_t)(m0 + row) * lda + kelem + seg * 8);
            cp_async16(dst + 8192u, Al + (size_t)(m0 + row) * lda + kelem + seg * 8);
        }
        // B tiles: 128 rows = 1024 segs; 4 per thread
#pragma unroll
        for (int i = 0; i < 4; i++) {
            int sidx = tid + i * 256;
            int row = sidx >> 3, seg = sidx & 7;
            uint32_t dst = tb + 16384u + row * 128 + ((seg ^ (row & 7)) << 4);
            cp_async16(dst, Bh + (size_t)(n0 + row) * ldb + kelem + seg * 8);
            cp_async16(dst + 16384u, Bl + (size_t)(n0 + row) * ldb + kelem + seg * 8);
        }
    };

    float acc[2][4][4];
#pragma unroll
    for (int i = 0; i < 2; i++)
#pragma unroll
        for (int j = 0; j < 4; j++)
#pragma unroll
            for (int q = 0; q < 4; q++) acc[i][j][q] = 0.f;

    issue(0, kbeg);
    CP_COMMIT();

    int rin = lane & 15, sadd = lane >> 4;                       // A ldmatrix mapping
    int brow = warp_n * 32 + ((lane >> 3) << 3) + (lane & 7);    // B ldmatrix mapping
    int bxor = brow & 7;
    uint32_t brow_off = (uint32_t)brow * 128;

    for (int c = 0; c < kchunks; c++) {
        CP_WAIT0();
        __syncthreads();
        if (c + 1 < kchunks) {
            issue((c + 1) & 1, kbeg + (c + 1) * 64);
            CP_COMMIT();
        }
        uint32_t tb = sb + (uint32_t)(c & 1) * 49152u;
#pragma unroll
        for (int kk = 0; kk < 4; kk++) {
            uint32_t ah[2][4], al[2][4];
#pragma unroll
            for (int mi = 0; mi < 2; mi++) {
                int row = warp_m * 32 + mi * 16 + rin;
                uint32_t off = (uint32_t)row * 128 + (((2 * kk + sadd) ^ (row & 7)) << 4);
                ldsm_x4(ah[mi], tb + off);
                ldsm_x4(al[mi], tb + 8192u + off);
            }
            uint32_t bh_lo[4], bh_hi[4], bl_lo[4], bl_hi[4];
            {
                uint32_t off_lo = brow_off + (((2 * kk) ^ bxor) << 4);
                uint32_t off_hi = brow_off + (((2 * kk + 1) ^ bxor) << 4);
                ldsm_x4(bh_lo, tb + 16384u + off_lo);
                ldsm_x4(bh_hi, tb + 16384u + off_hi);
                ldsm_x4(bl_lo, tb + 32768u + off_lo);
                ldsm_x4(bl_hi, tb + 32768u + off_hi);
            }
#pragma unroll
            for (int mi = 0; mi < 2; mi++)
#pragma unroll
                for (int ni = 0; ni < 4; ni++) {
                    mma16816(acc[mi][ni], ah[mi], bh_lo[ni], bh_hi[ni]);
                    mma16816(acc[mi][ni], ah[mi], bl_lo[ni], bl_hi[ni]);
                    mma16816(acc[mi][ni], al[mi], bh_lo[ni], bh_hi[ni]);
                }
        }
        __syncthreads();
    }

    // epilogue: write fp32 partials
    float* cb = part + (size_t)blockIdx.z * NROI * ldp;
    int cr = lane >> 2, cc = (lane & 3) * 2;
#pragma unroll
    for (int mi = 0; mi < 2; mi++) {
        int mrow = m0 + warp_m * 32 + mi * 16 + cr;
#pragma unroll
        for (int ni = 0; ni < 4; ni++) {
            int ncol = n0 + warp_n * 32 + ni * 8 + cc;
            *(float2*)(cb + (size_t)mrow * ldp + ncol) =
                make_float2(acc[mi][ni][0], acc[mi][ni][1]);
            *(float2*)(cb + (size_t)(mrow + 8) * ldp + ncol) =
                make_float2(acc[mi][ni][2], acc[mi][ni][3]);
        }
    }
}

// ---------------- split-K reduce + bias + act ----------------
__global__ void k_reduceA(const float* __restrict__ part,
                          const float* __restrict__ b1,
                          const float* __restrict__ bm1) {
    int i = blockIdx.x * 256 + threadIdx.x;   // over 256*2048
    int n = i & 2047;
    int mm = i >> 11;
    float v = part[i] + part[NROI * 2048 + i];
    if (n < 1024) {
        float r = fmaxf(v + b1[n], 0.f);
        __nv_bfloat16 h = __float2bfloat16(r);
        size_t o = (size_t)mm * 1024 + n;
        g_h1h[o] = h;
        g_h1l[o] = __float2bfloat16(r - __bfloat162float(h));
    } else {
        g_m[(size_t)mm * 1024 + (n - 1024)] = fmaxf(v + bm1[n - 1024], 0.f);
    }
}

__global__ void k_reduceB(const float* __restrict__ part,
                          const float* __restrict__ bias) {
    int i = blockIdx.x * 256 + threadIdx.x;   // over 256*1024
    const int S = NROI * DFF;
    float v = part[i] + part[S + i] + part[2 * S + i] + part[3 * S + i];
    g_h2[i] = fmaxf(v + bias[i & 1023], 0.f);
}

// ---------------- fused head GEMMs: offset (N=98) & mask (N=49) ----------------
__global__ void k_heads(const float* __restrict__ w3, const float* __restrict__ b3,
                        const float* __restrict__ wm2, const float* __restrict__ bm2) {
    __shared__ float As[8][128];
    int which = blockIdx.y;
    const float* A = which ? g_m : g_h2;
    const float* Bm = which ? wm2 : w3;
    const float* bias = which ? bm2 : b3;
    int Nn = which ? 49 : 98;
    int tid = threadIdx.x;
    int m0 = blockIdx.x * 8;
    float acc[8];
#pragma unroll
    for (int q = 0; q < 8; q++) acc[q] = 0.f;

    for (int kc = 0; kc < DFF; kc += 128) {
#pragma unroll
        for (int q = 0; q < 8; q++)
            As[q][tid] = A[(size_t)(m0 + q) * DFF + kc + tid];
        __syncthreads();
        if (tid < Nn) {
            for (int k = 0; k < 128; k++) {
                float bv = Bm[(size_t)(kc + k) * Nn + tid];
#pragma unroll
                for (int q = 0; q < 8; q++) acc[q] += As[q][k] * bv;
            }
        }
        __syncthreads();
    }
    if (tid < Nn) {
        float bb = bias[tid];
#pragma unroll
        for (int q = 0; q < 8; q++) {
            float v = acc[q] + bb;
            if (which) g_mask[(size_t)(m0 + q) * 49 + tid] = 1.0f / (1.0f + expf(-v));
            else       g_off[(size_t)(m0 + q) * 98 + tid] = v;
        }
    }
}

// ---------------- launch ----------------
extern "C" void kernel_launch(void* const* d_in, const int* in_sizes, int n_in,
                              void* d_out, int out_size) {
    const float* data = (const float*)d_in[0];
    const float* rois = (const float*)d_in[1];
    const float* w1   = (const float*)d_in[2];
    const float* b1   = (const float*)d_in[3];
    const float* w2   = (const float*)d_in[4];
    const float* b2   = (const float*)d_in[5];
    const float* w3   = (const float*)d_in[6];
    const float* b3   = (const float*)d_in[7];
    const float* wm1  = (const float*)d_in[8];
    const float* bm1  = (const float*)d_in[9];
    const float* wm2  = (const float*)d_in[10];
    const float* bm2  = (const float*)d_in[11];
    float* out = (float*)d_out;

    void *pxh, *pxl, *pbt1h, *pbt1l, *pbt2h, *pbt2l, *pp1, *ph1h, *ph1l, *pp2, *poff, *pmask;
    cudaGetSymbolAddress(&pxh,   g_xh);
    cudaGetSymbolAddress(&pxl,   g_xl);
    cudaGetSymbolAddress(&pbt1h, g_bt1h);
    cudaGetSymbolAddress(&pbt1l, g_bt1l);
    cudaGetSymbolAddress(&pbt2h, g_bt2h);
    cudaGetSymbolAddress(&pbt2l, g_bt2l);
    cudaGetSymbolAddress(&pp1,   g_p1);
    cudaGetSymbolAddress(&ph1h,  g_h1h);
    cudaGetSymbolAddress(&ph1l,  g_h1l);
    cudaGetSymbolAddress(&pp2,   g_p2);
    cudaGetSymbolAddress(&poff,  g_off);
    cudaGetSymbolAddress(&pmask, g_mask);

    cudaFuncSetAttribute(k_mma, cudaFuncAttributeMaxDynamicSharedMemorySize, 98304);

    // 1) NCHW -> NHWC
    k_nchw2nhwc<<<dim3(HWSZ / 32, CCH / 32, 2), dim3(32, 8)>>>(data);

    // 2) weight conversions (transpose + bf16 hi/lo)
    k_cvt_t<<<dim3(KX / 32, 1024 / 32), dim3(32, 8)>>>(w1, 1024,
        (__nv_bfloat16*)pbt1h, (__nv_bfloat16*)pbt1l, KX);
    k_cvt_t<<<dim3(KX / 32, 1024 / 32), dim3(32, 8)>>>(wm1, 1024,
        (__nv_bfloat16*)pbt1h + (size_t)1024 * KX, (__nv_bfloat16*)pbt1l + (size_t)1024 * KX, KX);
    k_cvt_t<<<dim3(DFF / 32, DFF / 32), dim3(32, 8)>>>(w2, DFF,
        (__nv_bfloat16*)pbt2h, (__nv_bfloat16*)pbt2l, DFF);

    // 3) pool #1 -> x (bf16 hi/lo)
    k_pool<<<NROI * NBIN, 32>>>(rois, nullptr, nullptr,
        (__nv_bfloat16*)pxh, (__nv_bfloat16*)pxl, nullptr);

    // 4) GEMM1: x @ [w1|wm1]  (M=256, N=2048, K=6272), split-K=2, 49 chunks each
    k_mma<<<dim3(16, 4, 2), 256, 98304>>>(
        (const __nv_bfloat16*)pxh, (const __nv_bfloat16*)pxl, KX,
        (const __nv_bfloat16*)pbt1h, (const __nv_bfloat16*)pbt1l, KX,
        49, (float*)pp1, 2048);
    k_reduceA<<<2048, 256>>>((const float*)pp1, b1, bm1);

    // 5) GEMM2: h1 @ w2  (M=256, N=1024, K=1024), split-K=4, 4 chunks each
    k_mma<<<dim3(8, 4, 4), 256, 98304>>>(
        (const __nv_bfloat16*)ph1h, (const __nv_bfloat16*)ph1l, DFF,
        (const __nv_bfloat16*)pbt2h, (const __nv_bfloat16*)pbt2l, DFF,
        4, (float*)pp2, 1024);
    k_reduceB<<<1024, 256>>>((const float*)pp2, b2);

    // 6) heads: offset = h2@w3+b3 ; mask = sigmoid(m@wm2+bm2)
    k_heads<<<dim3(32, 2), 128>>>(w3, b3, wm2, bm2);

    // 7) pool #2 with offsets, * mask -> out
    k_pool<<<NROI * NBIN, 32>>>(rois, (const float*)poff, (const float*)pmask,
        nullptr, nullptr, out);
}